// round 3
// baseline (speedup 1.0000x reference)
#include <cuda_runtime.h>

// SpectrogramAugmentation: B=64, C=2, F=128, T=2048, fp32. HBM-bound (traffic floor reached).
// R3: 256-bit vector ld/st (sm_100+ v8.f32) — each thread owns exactly 8 consecutive
// floats of a row; one v8 load per input buffer, one v8 store. Streaming (.cs) hints.
// Traffic-minimal branches:
//   - non-apply batches: out = spec (no noise read)
//   - apply + freq-masked rows: out = 0.01*noise (no spec read)
//   - apply + kept rows: out = (timekeep? spec:0) + 0.01*noise

#define SA_B 64
#define SA_C 2
#define SA_F 128
#define SA_T 2048
#define SA_FREQ_PARAM 20.0f
#define SA_TIME_PARAM 40.0f
#define SA_NOISE_STD 0.01f
#define SA_P_APPLY 0.5f

struct f8 { float v[8]; };

__device__ __forceinline__ f8 ldg256cs(const float* p) {
    f8 r;
    asm volatile("ld.global.cs.v8.f32 {%0,%1,%2,%3,%4,%5,%6,%7}, [%8];"
                 : "=f"(r.v[0]), "=f"(r.v[1]), "=f"(r.v[2]), "=f"(r.v[3]),
                   "=f"(r.v[4]), "=f"(r.v[5]), "=f"(r.v[6]), "=f"(r.v[7])
                 : "l"(p));
    return r;
}

__device__ __forceinline__ void stg256cs(float* p, const f8& r) {
    asm volatile("st.global.cs.v8.f32 [%0], {%1,%2,%3,%4,%5,%6,%7,%8};"
                 :: "l"(p),
                    "f"(r.v[0]), "f"(r.v[1]), "f"(r.v[2]), "f"(r.v[3]),
                    "f"(r.v[4]), "f"(r.v[5]), "f"(r.v[6]), "f"(r.v[7])
                 : "memory");
}

__global__ __launch_bounds__(256)
void specaug_kernel(const float* __restrict__ spec,
                    const float* __restrict__ apply_u,
                    const float* __restrict__ f_width_u,
                    const float* __restrict__ f_start_u,
                    const float* __restrict__ t_width_u,
                    const float* __restrict__ t_start_u,
                    const float* __restrict__ noise,
                    float* __restrict__ out) {
    const int row = blockIdx.x;                 // b*C*F + c*F + f
    const int f   = row & (SA_F - 1);
    const int b   = row / (SA_C * SA_F);
    const long long base = (long long)row * SA_T;
    const int t0 = threadIdx.x * 8;             // this thread's 8 time samples

    const float* sp = spec + base + t0;
    float*       op = out  + base + t0;

    const bool apply = (apply_u[b] <= SA_P_APPLY);
    if (!apply) {
        // exact passthrough: no noise read
        stg256cs(op, ldg256cs(sp));
        return;
    }

    const float* np = noise + base + t0;

    // --- frequency mask for this f (2 masks, no clamp_min_one) ---
    bool fhit = false;
    #pragma unroll
    for (int k = 0; k < 2; k++) {
        const int   w   = (int)floorf(f_width_u[b * 2 + k] * SA_FREQ_PARAM);
        const float rng = (float)(SA_F - w);
        const int   s0  = (int)floorf(f_start_u[b * 2 + k] * rng);
        fhit = fhit || (f >= s0 && f < s0 + w);
    }

    if (fhit) {
        // whole row frequency-masked: out = 0.01*noise, no spec read
        f8 n = ldg256cs(np);
        f8 o;
        #pragma unroll
        for (int j = 0; j < 8; j++) o.v[j] = n.v[j] * SA_NOISE_STD;
        stg256cs(op, o);
        return;
    }

    // --- time masks (2 masks, clamp_min_one on range) ---
    int ts0[2], te[2];
    #pragma unroll
    for (int k = 0; k < 2; k++) {
        const int   w   = (int)floorf(t_width_u[b * 2 + k] * SA_TIME_PARAM);
        float rng = (float)(SA_T - w);
        if (rng < 1.0f) rng = 1.0f;
        const int s0 = (int)floorf(t_start_u[b * 2 + k] * rng);
        ts0[k] = s0;
        te[k]  = s0 + w;
    }

    const f8 s = ldg256cs(sp);
    const f8 n = ldg256cs(np);
    f8 o;
    #pragma unroll
    for (int j = 0; j < 8; j++) {
        const int t = t0 + j;
        const bool thit = (t >= ts0[0] && t < te[0]) ||
                          (t >= ts0[1] && t < te[1]);
        o.v[j] = fmaf(n.v[j], SA_NOISE_STD, thit ? 0.0f : s.v[j]);
    }
    stg256cs(op, o);
}

extern "C" void kernel_launch(void* const* d_in, const int* in_sizes, int n_in,
                              void* d_out, int out_size) {
    const float* spec      = (const float*)d_in[0];
    const float* apply_u   = (const float*)d_in[1];
    const float* f_width_u = (const float*)d_in[2];
    const float* f_start_u = (const float*)d_in[3];
    const float* t_width_u = (const float*)d_in[4];
    const float* t_start_u = (const float*)d_in[5];
    const float* noise     = (const float*)d_in[6];
    float* out             = (float*)d_out;

    const int rows = SA_B * SA_C * SA_F;   // 16384 blocks, 256 threads: 1 row each
    specaug_kernel<<<rows, 256>>>(spec, apply_u, f_width_u, f_start_u,
                                  t_width_u, t_start_u, noise, out);
}